// round 2
// baseline (speedup 1.0000x reference)
#include <cuda_runtime.h>

#define NBOX        1048576
#define BOX_PER_BLK 256
#define NBLOCKS     (NBOX / BOX_PER_BLK)   // 4096
#define PRED_F      18                      // floats per box in pred (9 pts * 2)
#define TGT_F       8                       // floats per box in target (4 pts * 2)

// Scratch (no device allocation allowed anywhere).
__device__ float        g_partials[NBLOCKS];
__device__ unsigned int g_ticket = 0;       // reset to 0 by the last block each launch

__global__ __launch_bounds__(BOX_PER_BLK)
void kld_fused_kernel(const float* __restrict__ pred, const float* __restrict__ tgt,
                      float* __restrict__ out)
{
    __shared__ float sp[BOX_PER_BLK * PRED_F];   // 18432 B
    __shared__ float st[BOX_PER_BLK * TGT_F];    //  8192 B
    __shared__ float red[8];
    __shared__ bool  is_last;
    __shared__ double dred[8];

    const int tid = threadIdx.x;
    const int blk = blockIdx.x;

    // ---- Coalesced staging: global -> shared via float4 ----
    {
        const float4* p4 = (const float4*)(pred + (size_t)blk * (BOX_PER_BLK * PRED_F));
        float4*       s4 = (float4*)sp;
        #pragma unroll
        for (int i = tid; i < (BOX_PER_BLK * PRED_F) / 4; i += BOX_PER_BLK)
            s4[i] = p4[i];

        const float4* t4 = (const float4*)(tgt + (size_t)blk * (BOX_PER_BLK * TGT_F));
        float4*       q4 = (float4*)st;
        #pragma unroll
        for (int i = tid; i < (BOX_PER_BLK * TGT_F) / 4; i += BOX_PER_BLK)
            q4[i] = t4[i];
    }
    __syncthreads();

    // ---- Per-box math ----
    const float* pb = sp + tid * PRED_F;
    const float* tb = st + tid * TGT_F;

    float mux = 0.f, muy = 0.f;
    #pragma unroll
    for (int k = 0; k < 9; ++k) { mux += pb[2*k]; muy += pb[2*k + 1]; }
    const float inv9 = 1.0f / 9.0f;
    mux *= inv9; muy *= inv9;

    float sxx = 0.f, sxy = 0.f, syy = 0.f;
    #pragma unroll
    for (int k = 0; k < 9; ++k) {
        float dx = pb[2*k]     - mux;
        float dy = pb[2*k + 1] - muy;
        sxx += dx * dx; sxy += dx * dy; syy += dy * dy;
    }
    const float GMM_EPS = 1e-6f;
    float pxx = sxx * inv9 + GMM_EPS;
    float pxy = sxy * inv9;
    float pyy = syy * inv9 + GMM_EPS;

    float x0 = tb[0], y0 = tb[1];
    float x1 = tb[2], y1 = tb[3];
    float x2 = tb[4], y2 = tb[5];
    float x3 = tb[6], y3 = tb[7];

    float tmux = (x0 + x1 + x2 + x3) * 0.25f;
    float tmuy = (y0 + y1 + y2 + y3) * 0.25f;

    float e1x = x1 - x0, e1y = y1 - y0;
    float e2x = x2 - x1, e2y = y2 - y1;
    float w = e1x * e1x + e1y * e1y;
    float h = e2x * e2x + e2y * e2y;

    float inv_sw = rsqrtf(w);
    float c = e1x * inv_sw;
    float s = e1y * inv_sw;

    const float invLL = 1.0f / 36.0f;     // 1/(4*L*L), L=3
    float d0 = w * invLL;
    float d1 = h * invLL;

    float txx = c * c * d0 + s * s * d1;
    float txy = c * s * (d0 - d1);
    float tyy = s * s * d0 + c * c * d1;

    float tdet = txx * tyy - txy * txy;
    float invd = 1.0f / tdet;
    float ixx =  tyy * invd;
    float ixy = -txy * invd;
    float iyy =  txx * invd;

    float dx = mux - tmux;
    float dy = muy - tmuy;

    float term1 = dx * dx * ixx + 2.0f * dx * dy * ixy + dy * dy * iyy;
    float trace = ixx * pxx + 2.0f * ixy * pxy + iyy * pyy;
    float pdet  = pxx * pyy - pxy * pxy;
    float term2 = trace + logf(tdet / pdet);

    float kld  = 0.5f * (term1 + term2) - 1.0f;
    float kl   = fmaxf(kld, 1e-6f);
    float loss = 1.0f - 1.0f / (2.0f + sqrtf(kl));

    // ---- Block reduction (deterministic tree) ----
    #pragma unroll
    for (int off = 16; off > 0; off >>= 1)
        loss += __shfl_down_sync(0xffffffffu, loss, off);

    if ((tid & 31) == 0) red[tid >> 5] = loss;
    __syncthreads();

    if (tid < 32) {
        float v = (tid < 8) ? red[tid] : 0.0f;
        #pragma unroll
        for (int off = 4; off > 0; off >>= 1)
            v += __shfl_down_sync(0xffffffffu, v, off);
        if (tid == 0) __stcg(&g_partials[blk], v);
    }

    // ---- Last block performs the final (deterministic, fixed-order) reduce ----
    if (tid == 0) {
        __threadfence();
        unsigned int prev = atomicAdd(&g_ticket, 1u);
        is_last = (prev == NBLOCKS - 1);
    }
    __syncthreads();

    if (is_last) {
        double acc = 0.0;
        #pragma unroll
        for (int i = tid; i < NBLOCKS; i += BOX_PER_BLK)
            acc += (double)__ldcg(&g_partials[i]);

        #pragma unroll
        for (int off = 16; off > 0; off >>= 1)
            acc += __shfl_down_sync(0xffffffffu, acc, off);

        if ((tid & 31) == 0) dred[tid >> 5] = acc;
        __syncthreads();

        if (tid < 32) {
            double v = (tid < 8) ? dred[tid] : 0.0;
            #pragma unroll
            for (int off = 4; off > 0; off >>= 1)
                v += __shfl_down_sync(0xffffffffu, v, off);
            if (tid == 0) {
                out[0] = (float)(v / (double)NBOX);
                g_ticket = 0;   // reset for next graph replay
            }
        }
    }
}

extern "C" void kernel_launch(void* const* d_in, const int* in_sizes, int n_in,
                              void* d_out, int out_size)
{
    const float* pred = (const float*)d_in[0];
    const float* tgt  = (const float*)d_in[1];
    float* out = (float*)d_out;

    kld_fused_kernel<<<NBLOCKS, BOX_PER_BLK>>>(pred, tgt, out);
}

// round 3
// speedup vs baseline: 1.0986x; 1.0986x over previous
#include <cuda_runtime.h>

#define NBOX        1048576
#define BOX_PER_BLK 256
#define NBLOCKS     (NBOX / BOX_PER_BLK)   // 4096
#define PRED_F      18                      // floats per box in pred (9 pts * 2)
#define TGT_F       8                       // floats per box in target (4 pts * 2)

// Scratch (no device allocation allowed anywhere).
__device__ double       g_sum    = 0.0;     // reset by last block each launch
__device__ unsigned int g_ticket = 0;       // reset by last block each launch

__global__ __launch_bounds__(BOX_PER_BLK)
void kld_fused_kernel(const float* __restrict__ pred, const float* __restrict__ tgt,
                      float* __restrict__ out)
{
    __shared__ float sp[BOX_PER_BLK * PRED_F];   // 18432 B
    __shared__ float st[BOX_PER_BLK * TGT_F];    //  8192 B
    __shared__ float red[8];

    const int tid = threadIdx.x;
    const int blk = blockIdx.x;

    // ---- Coalesced staging: global -> shared via float4 (streaming loads) ----
    {
        const float4* p4 = (const float4*)(pred + (size_t)blk * (BOX_PER_BLK * PRED_F));
        float4*       s4 = (float4*)sp;
        #pragma unroll
        for (int i = tid; i < (BOX_PER_BLK * PRED_F) / 4; i += BOX_PER_BLK)
            s4[i] = __ldcs(&p4[i]);

        const float4* t4 = (const float4*)(tgt + (size_t)blk * (BOX_PER_BLK * TGT_F));
        float4*       q4 = (float4*)st;
        #pragma unroll
        for (int i = tid; i < (BOX_PER_BLK * TGT_F) / 4; i += BOX_PER_BLK)
            q4[i] = __ldcs(&t4[i]);
    }
    __syncthreads();

    // ---- Per-box math ----
    const float* pb = sp + tid * PRED_F;
    const float* tb = st + tid * TGT_F;

    float mux = 0.f, muy = 0.f;
    #pragma unroll
    for (int k = 0; k < 9; ++k) { mux += pb[2*k]; muy += pb[2*k + 1]; }
    const float inv9 = 1.0f / 9.0f;
    mux *= inv9; muy *= inv9;

    float sxx = 0.f, sxy = 0.f, syy = 0.f;
    #pragma unroll
    for (int k = 0; k < 9; ++k) {
        float dx = pb[2*k]     - mux;
        float dy = pb[2*k + 1] - muy;
        sxx += dx * dx; sxy += dx * dy; syy += dy * dy;
    }
    const float GMM_EPS = 1e-6f;
    float pxx = sxx * inv9 + GMM_EPS;
    float pxy = sxy * inv9;
    float pyy = syy * inv9 + GMM_EPS;

    float x0 = tb[0], y0 = tb[1];
    float x1 = tb[2], y1 = tb[3];
    float x2 = tb[4], y2 = tb[5];
    float x3 = tb[6], y3 = tb[7];

    float tmux = (x0 + x1 + x2 + x3) * 0.25f;
    float tmuy = (y0 + y1 + y2 + y3) * 0.25f;

    float e1x = x1 - x0, e1y = y1 - y0;
    float e2x = x2 - x1, e2y = y2 - y1;
    float w = e1x * e1x + e1y * e1y;
    float h = e2x * e2x + e2y * e2y;

    float inv_sw = rsqrtf(w);
    float c = e1x * inv_sw;
    float s = e1y * inv_sw;

    const float invLL = 1.0f / 36.0f;     // 1/(4*L*L), L=3
    float d0 = w * invLL;
    float d1 = h * invLL;

    float txx = c * c * d0 + s * s * d1;
    float txy = c * s * (d0 - d1);
    float tyy = s * s * d0 + c * c * d1;

    float tdet = txx * tyy - txy * txy;
    float invd = 1.0f / tdet;
    float ixx =  tyy * invd;
    float ixy = -txy * invd;
    float iyy =  txx * invd;

    float dx = mux - tmux;
    float dy = muy - tmuy;

    float term1 = dx * dx * ixx + 2.0f * dx * dy * ixy + dy * dy * iyy;
    float trace = ixx * pxx + 2.0f * ixy * pxy + iyy * pyy;
    float pdet  = pxx * pyy - pxy * pxy;
    float term2 = trace + logf(tdet / pdet);

    float kld  = 0.5f * (term1 + term2) - 1.0f;
    float kl   = fmaxf(kld, 1e-6f);
    float loss = 1.0f - 1.0f / (2.0f + sqrtf(kl));

    // ---- Block reduction (deterministic tree) ----
    #pragma unroll
    for (int off = 16; off > 0; off >>= 1)
        loss += __shfl_down_sync(0xffffffffu, loss, off);

    if ((tid & 31) == 0) red[tid >> 5] = loss;
    __syncthreads();

    if (tid == 0) {
        float v = 0.f;
        #pragma unroll
        for (int i = 0; i < 8; ++i) v += red[i];

        // Relaxed L2 atomic accumulate; same-address serialization gives
        // visibility without any fence.
        double old = atomicAdd(&g_sum, (double)v);

        // Data-dependent increment: the ticket RMW cannot issue before the
        // g_sum RMW has performed at L2.
        unsigned int inc = 1u + (unsigned int)(__double_as_longlong(old) & 0ll);
        unsigned int prev = atomicAdd(&g_ticket, inc);

        if (prev == NBLOCKS - 1) {
            // All 4096 adds to g_sum are performed at L2; read via same-address RMW.
            double total = atomicAdd(&g_sum, 0.0);
            out[0] = (float)(total / (double)NBOX);
            // Reset for next graph replay (kernel boundary publishes these).
            g_sum    = 0.0;
            g_ticket = 0u;
        }
    }
}

extern "C" void kernel_launch(void* const* d_in, const int* in_sizes, int n_in,
                              void* d_out, int out_size)
{
    const float* pred = (const float*)d_in[0];
    const float* tgt  = (const float*)d_in[1];
    float* out = (float*)d_out;

    kld_fused_kernel<<<NBLOCKS, BOX_PER_BLK>>>(pred, tgt, out);
}

// round 4
// speedup vs baseline: 1.3435x; 1.2229x over previous
#include <cuda_runtime.h>

#define NBOX        1048576
#define BOX_PER_BLK 256
#define GRID_BLKS   1024
#define TILES       4                       // GRID_BLKS * TILES * BOX_PER_BLK == NBOX
#define PRED_F      18                      // floats per box in pred (9 pts * 2)
#define TGT_F       8                       // floats per box in target (4 pts * 2)
#define PRED_V4     ((BOX_PER_BLK * PRED_F) / 4)   // 1152 float4 per tile

// Scratch (no device allocation allowed anywhere).
__device__ double       g_sum    = 0.0;     // reset by last block each launch
__device__ unsigned int g_ticket = 0;       // reset by last block each launch

__device__ __forceinline__ float box_loss(const float* __restrict__ pb,
                                          float4 q0, float4 q1)
{
    // ---- target side (registers only) ----
    float x0 = q0.x, y0 = q0.y, x1 = q0.z, y1 = q0.w;
    float x2 = q1.x, y2 = q1.y, x3 = q1.z, y3 = q1.w;

    float tmux = (x0 + x1 + x2 + x3) * 0.25f;
    float tmuy = (y0 + y1 + y2 + y3) * 0.25f;

    float e1x = x1 - x0, e1y = y1 - y0;
    float e2x = x2 - x1, e2y = y2 - y1;
    float w = e1x * e1x + e1y * e1y;
    float h = e2x * e2x + e2y * e2y;

    float inv_sw = rsqrtf(w);
    float c = e1x * inv_sw;
    float s = e1y * inv_sw;

    const float invLL = 1.0f / 36.0f;     // 1/(4*L*L), L=3
    float d0 = w * invLL;
    float d1 = h * invLL;

    float txx = c * c * d0 + s * s * d1;
    float txy = c * s * (d0 - d1);
    float tyy = s * s * d0 + c * c * d1;

    float tdet = txx * tyy - txy * txy;
    float invd = 1.0f / tdet;
    float ixx =  tyy * invd;
    float ixy = -txy * invd;
    float iyy =  txx * invd;

    // ---- pred side (from shared) ----
    float mux = 0.f, muy = 0.f;
    #pragma unroll
    for (int k = 0; k < 9; ++k) { mux += pb[2*k]; muy += pb[2*k + 1]; }
    const float inv9 = 1.0f / 9.0f;
    mux *= inv9; muy *= inv9;

    float sxx = 0.f, sxy = 0.f, syy = 0.f;
    #pragma unroll
    for (int k = 0; k < 9; ++k) {
        float ddx = pb[2*k]     - mux;
        float ddy = pb[2*k + 1] - muy;
        sxx += ddx * ddx; sxy += ddx * ddy; syy += ddy * ddy;
    }
    const float GMM_EPS = 1e-6f;
    float pxx = sxx * inv9 + GMM_EPS;
    float pxy = sxy * inv9;
    float pyy = syy * inv9 + GMM_EPS;

    float dx = mux - tmux;
    float dy = muy - tmuy;

    float term1 = dx * dx * ixx + 2.0f * dx * dy * ixy + dy * dy * iyy;
    float trace = ixx * pxx + 2.0f * ixy * pxy + iyy * pyy;
    float pdet  = pxx * pyy - pxy * pxy;
    float term2 = trace + logf(tdet / pdet);

    float kld  = 0.5f * (term1 + term2) - 1.0f;
    float kl   = fmaxf(kld, 1e-6f);
    return 1.0f - 1.0f / (2.0f + sqrtf(kl));
}

__global__ __launch_bounds__(BOX_PER_BLK)
void kld_fused_kernel(const float* __restrict__ pred, const float* __restrict__ tgt,
                      float* __restrict__ out)
{
    __shared__ float sp[BOX_PER_BLK * PRED_F];   // 18432 B (pred tile)
    __shared__ float red[8];

    const int tid = threadIdx.x;
    const int blk = blockIdx.x;

    // prefetch registers for the pipeline
    float4 rp[5];        // pred staging (4.5 float4/thread, last predicated)
    float4 q0, q1;       // target box (direct, 16B-aligned per box)

    // ---- prefetch tile 0 ----
    {
        const int tile = blk;
        const float4* p4 = (const float4*)(pred + (size_t)tile * (BOX_PER_BLK * PRED_F));
        #pragma unroll
        for (int u = 0; u < 5; ++u) {
            int i = tid + u * BOX_PER_BLK;
            if (i < PRED_V4) rp[u] = __ldcs(&p4[i]);
        }
        const float4* t4 = (const float4*)(tgt + (size_t)tile * (BOX_PER_BLK * TGT_F)) + tid * 2;
        q0 = __ldcs(&t4[0]);
        q1 = __ldcs(&t4[1]);
    }

    float acc = 0.0f;

    #pragma unroll
    for (int it = 0; it < TILES; ++it) {
        // stage current pred tile to shared
        {
            float4* s4 = (float4*)sp;
            #pragma unroll
            for (int u = 0; u < 5; ++u) {
                int i = tid + u * BOX_PER_BLK;
                if (i < PRED_V4) s4[i] = rp[u];
            }
        }
        __syncthreads();

        float4 cq0 = q0, cq1 = q1;

        // prefetch next tile while computing this one
        if (it + 1 < TILES) {
            const int tile = blk + (it + 1) * GRID_BLKS;
            const float4* p4 = (const float4*)(pred + (size_t)tile * (BOX_PER_BLK * PRED_F));
            #pragma unroll
            for (int u = 0; u < 5; ++u) {
                int i = tid + u * BOX_PER_BLK;
                if (i < PRED_V4) rp[u] = __ldcs(&p4[i]);
            }
            const float4* t4 = (const float4*)(tgt + (size_t)tile * (BOX_PER_BLK * TGT_F)) + tid * 2;
            q0 = __ldcs(&t4[0]);
            q1 = __ldcs(&t4[1]);
        }

        acc += box_loss(sp + tid * PRED_F, cq0, cq1);

        __syncthreads();   // protect sp before next iteration's staging
    }

    // ---- Block reduction (deterministic tree) ----
    #pragma unroll
    for (int off = 16; off > 0; off >>= 1)
        acc += __shfl_down_sync(0xffffffffu, acc, off);

    if ((tid & 31) == 0) red[tid >> 5] = acc;
    __syncthreads();

    if (tid == 0) {
        float v = 0.f;
        #pragma unroll
        for (int i = 0; i < 8; ++i) v += red[i];

        // Relaxed L2 atomic accumulate; same-address serialization gives
        // visibility without any fence.
        double old = atomicAdd(&g_sum, (double)v);

        // Data-dependent increment: ticket RMW can't issue before g_sum RMW performed.
        unsigned int inc = 1u + (unsigned int)(__double_as_longlong(old) & 0ll);
        unsigned int prev = atomicAdd(&g_ticket, inc);

        if (prev == GRID_BLKS - 1) {
            double total = atomicAdd(&g_sum, 0.0);
            out[0] = (float)(total / (double)NBOX);
            g_sum    = 0.0;
            g_ticket = 0u;
        }
    }
}

extern "C" void kernel_launch(void* const* d_in, const int* in_sizes, int n_in,
                              void* d_out, int out_size)
{
    const float* pred = (const float*)d_in[0];
    const float* tgt  = (const float*)d_in[1];
    float* out = (float*)d_out;

    kld_fused_kernel<<<GRID_BLKS, BOX_PER_BLK>>>(pred, tgt, out);
}

// round 6
// speedup vs baseline: 1.7742x; 1.3206x over previous
#include <cuda_runtime.h>
#include <cstdint>

#define NBOX        1048576
#define BOX_PER_BLK 256
#define GRID_BLKS   1024
#define TILES       4                       // GRID_BLKS * TILES * BOX_PER_BLK == NBOX
#define PRED_F      18                      // floats per box in pred (9 pts * 2)
#define TGT_F       8                       // floats per box in target (4 pts * 2)
#define SP_TILE     (BOX_PER_BLK * PRED_F)          // 4608 floats = 18432 B
#define PRED_V4     (SP_TILE / 4)                   // 1152 float4 per tile

// Scratch (no device allocation allowed anywhere).
__device__ double       g_sum    = 0.0;     // reset by last block each launch
__device__ unsigned int g_ticket = 0;       // reset by last block each launch

__device__ __forceinline__ void cp_async16(float* smem_dst, const float4* gmem_src)
{
    unsigned int s = (unsigned int)__cvta_generic_to_shared(smem_dst);
    asm volatile("cp.async.cg.shared.global [%0], [%1], 16;\n"
                 :: "r"(s), "l"(gmem_src) : "memory");
}
__device__ __forceinline__ void cp_commit()
{
    asm volatile("cp.async.commit_group;\n" ::: "memory");
}
template <int N>
__device__ __forceinline__ void cp_wait()
{
    asm volatile("cp.async.wait_group %0;\n" :: "n"(N) : "memory");
}

__device__ __forceinline__ float box_loss(const float* __restrict__ pb,
                                          float4 q0, float4 q1)
{
    // ---- target side (registers only) ----
    float x0 = q0.x, y0 = q0.y, x1 = q0.z, y1 = q0.w;
    float x2 = q1.x, y2 = q1.y, x3 = q1.z, y3 = q1.w;

    float tmux = (x0 + x1 + x2 + x3) * 0.25f;
    float tmuy = (y0 + y1 + y2 + y3) * 0.25f;

    float e1x = x1 - x0, e1y = y1 - y0;
    float e2x = x2 - x1, e2y = y2 - y1;
    float w = e1x * e1x + e1y * e1y;
    float h = e2x * e2x + e2y * e2y;

    float inv_sw = rsqrtf(w);
    float c = e1x * inv_sw;
    float s = e1y * inv_sw;

    const float invLL = 1.0f / 36.0f;     // 1/(4*L*L), L=3
    float d0 = w * invLL;
    float d1 = h * invLL;

    float txx = c * c * d0 + s * s * d1;
    float txy = c * s * (d0 - d1);
    float tyy = s * s * d0 + c * c * d1;

    float tdet = txx * tyy - txy * txy;
    float invd = 1.0f / tdet;
    float ixx =  tyy * invd;
    float ixy = -txy * invd;
    float iyy =  txx * invd;

    // ---- pred side (from shared) ----
    float mux = 0.f, muy = 0.f;
    #pragma unroll
    for (int k = 0; k < 9; ++k) { mux += pb[2*k]; muy += pb[2*k + 1]; }
    const float inv9 = 1.0f / 9.0f;
    mux *= inv9; muy *= inv9;

    float sxx = 0.f, sxy = 0.f, syy = 0.f;
    #pragma unroll
    for (int k = 0; k < 9; ++k) {
        float ddx = pb[2*k]     - mux;
        float ddy = pb[2*k + 1] - muy;
        sxx += ddx * ddx; sxy += ddx * ddy; syy += ddy * ddy;
    }
    const float GMM_EPS = 1e-6f;
    float pxx = sxx * inv9 + GMM_EPS;
    float pxy = sxy * inv9;
    float pyy = syy * inv9 + GMM_EPS;

    float dx = mux - tmux;
    float dy = muy - tmuy;

    float term1 = dx * dx * ixx + 2.0f * dx * dy * ixy + dy * dy * iyy;
    float trace = ixx * pxx + 2.0f * ixy * pxy + iyy * pyy;
    float pdet  = pxx * pyy - pxy * pxy;
    float term2 = trace + logf(tdet / pdet);

    float kld  = 0.5f * (term1 + term2) - 1.0f;
    float kl   = fmaxf(kld, 1e-6f);
    return 1.0f - 1.0f / (2.0f + sqrtf(kl));
}

__global__ __launch_bounds__(BOX_PER_BLK)
void kld_fused_kernel(const float* __restrict__ pred, const float* __restrict__ tgt,
                      float* __restrict__ out)
{
    __shared__ float sp[2][SP_TILE];             // 2 x 18432 B (pred double buffer)
    __shared__ float red[8];

    const int tid = threadIdx.x;
    const int blk = blockIdx.x;

    // ---- issue async copy of pred tile 0, prefetch tgt tile 0 to regs ----
    {
        const float4* p4 = (const float4*)(pred + (size_t)blk * SP_TILE);
        #pragma unroll
        for (int u = 0; u < 5; ++u) {
            int i = tid + u * BOX_PER_BLK;
            if (i < PRED_V4) cp_async16(&sp[0][i * 4], &p4[i]);
        }
        cp_commit();
    }
    const float4* t4_0 = (const float4*)(tgt + (size_t)blk * (BOX_PER_BLK * TGT_F)) + tid * 2;
    float4 q0 = __ldcs(&t4_0[0]);
    float4 q1 = __ldcs(&t4_0[1]);

    float acc = 0.0f;

    #pragma unroll
    for (int it = 0; it < TILES; ++it) {
        const int cur = it & 1;
        float4 nq0, nq1;

        // issue next tile's async copy + tgt prefetch while current computes
        if (it + 1 < TILES) {
            const int tile = blk + (it + 1) * GRID_BLKS;
            const float4* p4 = (const float4*)(pred + (size_t)tile * SP_TILE);
            #pragma unroll
            for (int u = 0; u < 5; ++u) {
                int i = tid + u * BOX_PER_BLK;
                if (i < PRED_V4) cp_async16(&sp[1 - cur][i * 4], &p4[i]);
            }
            cp_commit();
            const float4* t4 = (const float4*)(tgt + (size_t)tile * (BOX_PER_BLK * TGT_F)) + tid * 2;
            nq0 = __ldcs(&t4[0]);
            nq1 = __ldcs(&t4[1]);
        }

        // wait for the current tile's copy (leave the just-issued group in flight)
        if (it + 1 < TILES) cp_wait<1>(); else cp_wait<0>();
        __syncthreads();

        acc += box_loss(&sp[cur][tid * PRED_F], q0, q1);
        q0 = nq0; q1 = nq1;

        __syncthreads();   // all readers done with sp[cur] before it is re-filled
    }

    // ---- Block reduction (deterministic tree) ----
    #pragma unroll
    for (int off = 16; off > 0; off >>= 1)
        acc += __shfl_down_sync(0xffffffffu, acc, off);

    if ((tid & 31) == 0) red[tid >> 5] = acc;
    __syncthreads();

    if (tid == 0) {
        float v = 0.f;
        #pragma unroll
        for (int i = 0; i < 8; ++i) v += red[i];

        // Relaxed L2 atomic accumulate; same-address serialization gives
        // visibility without any fence.
        double old = atomicAdd(&g_sum, (double)v);

        // Data-dependent increment: ticket RMW can't issue before g_sum RMW performed.
        unsigned int inc = 1u + (unsigned int)(__double_as_longlong(old) & 0ll);
        unsigned int prev = atomicAdd(&g_ticket, inc);

        if (prev == GRID_BLKS - 1) {
            double total = atomicAdd(&g_sum, 0.0);
            out[0] = (float)(total / (double)NBOX);
            g_sum    = 0.0;
            g_ticket = 0u;
        }
    }
}

extern "C" void kernel_launch(void* const* d_in, const int* in_sizes, int n_in,
                              void* d_out, int out_size)
{
    const float* pred = (const float*)d_in[0];
    const float* tgt  = (const float*)d_in[1];
    float* out = (float*)d_out;

    kld_fused_kernel<<<GRID_BLKS, BOX_PER_BLK>>>(pred, tgt, out);
}